// round 16
// baseline (speedup 1.0000x reference)
#include <cuda_runtime.h>
#include <cuda_fp16.h>
#include <cstdint>

// ---------------- problem constants ----------------
#define IN_F   4096
#define OUT_F  4096
#define M_TOT  8192
#define BK     128          // k per iteration (= one scale group, 256B rows)
#define KITERS (IN_F / BK)  // 32
#define BM     128
#define BN     128
#define NTH    128          // 4 warps, each M128 x N32

// ---------------- static device scratch ----------------
// Z-packed inverted sign words, COLUMN-MAJOR kwords: g_packT[o*128 + kw]
//   bit j    (j<16) = 1 iff weight(o, 32kw + 2j)   < 0
//   bit 16+j (j<16) = 1 iff weight(o, 32kw + 2j+1) < 0
__device__ uint32_t g_packT[(size_t)OUT_F * (IN_F / 32)];   // 2 MB
__device__ __half   g_xh[(size_t)M_TOT * IN_F];             // 64 MB
// per (kgroup, o): half2(s, s) as uint32, transposed [kg][o]
__device__ uint32_t g_ppT[(size_t)(IN_F / 128) * OUT_F];    // 512 KB

// ---------------- SMEM stage layout (bytes) ----------------
// A: 32768 (128 rows x 256B, 16 chunks, xor-8 swizzle)
// W: 2048  (128 cols x 16B = 4 kwords each)
// S: 512   (128 cols x 4B half2 scale)
#define STG_A      0
#define STG_W      32768
#define STG_S      34816
#define STG_STRIDE 35328
#define STAGES     3
#define SM_TOTAL   (STAGES * STG_STRIDE)   // 105984

// ---------------- helpers ----------------
static __device__ __forceinline__ uint32_t smem_u32(const void* p) {
    uint32_t a;
    asm("{ .reg .u64 t; cvta.to.shared.u64 t, %1; cvt.u32.u64 %0, t; }"
        : "=r"(a) : "l"(p));
    return a;
}

#define CP_ASYNC16(dst, src) \
    asm volatile("cp.async.cg.shared.global [%0], [%1], 16;" :: "r"(dst), "l"(src))
#define CP_COMMIT()  asm volatile("cp.async.commit_group;" ::: "memory")
#define CP_WAIT1()   asm volatile("cp.async.wait_group 1;" ::: "memory")

static __device__ __forceinline__ void ldsm_x4(uint32_t* r, uint32_t addr) {
    asm volatile("ldmatrix.sync.aligned.m8n8.x4.shared.b16 {%0,%1,%2,%3}, [%4];"
                 : "=r"(r[0]), "=r"(r[1]), "=r"(r[2]), "=r"(r[3]) : "r"(addr));
}

static __device__ __forceinline__ void mma_fp16(float* d, const uint32_t* a,
                                                uint32_t b0, uint32_t b1) {
    asm("mma.sync.aligned.m16n8k16.row.col.f32.f16.f16.f32 "
        "{%0,%1,%2,%3}, {%4,%5,%6,%7}, {%8,%9}, {%0,%1,%2,%3};"
        : "+f"(d[0]), "+f"(d[1]), "+f"(d[2]), "+f"(d[3])
        : "r"(a[0]), "r"(a[1]), "r"(a[2]), "r"(a[3]), "r"(b0), "r"(b1));
}

// ============================================================
// Fused prep kernel, grid-sectioned
// ============================================================
#define PREP_CONVERT_BLOCKS 16384
#define PREP_SIGN_BLOCKS    8192
#define PREP_SCALE_BLOCKS   512
#define PREP_GRID (PREP_CONVERT_BLOCKS + PREP_SIGN_BLOCKS + PREP_SCALE_BLOCKS)

__global__ void __launch_bounds__(256)
prep_kernel(const float4* __restrict__ x4,
            const float* __restrict__ sw,
            const float* __restrict__ scales) {
    const int b = blockIdx.x;
    const int tid = threadIdx.x;

    if (b < PREP_CONVERT_BLOCKS) {
        size_t i = (size_t)b * 256 + tid;        // 8 floats each
        float4 a = x4[2 * i];
        float4 c = x4[2 * i + 1];
        __half2 h0 = __floats2half2_rn(a.x, a.y);
        __half2 h1 = __floats2half2_rn(a.z, a.w);
        __half2 h2 = __floats2half2_rn(c.x, c.y);
        __half2 h3 = __floats2half2_rn(c.z, c.w);
        uint4 q;
        q.x = *reinterpret_cast<uint32_t*>(&h0);
        q.y = *reinterpret_cast<uint32_t*>(&h1);
        q.z = *reinterpret_cast<uint32_t*>(&h2);
        q.w = *reinterpret_cast<uint32_t*>(&h3);
        *reinterpret_cast<uint4*>(&g_xh[i * 8]) = q;
    } else if (b < PREP_CONVERT_BLOCKS + PREP_SIGN_BLOCKS) {
        const int bb = b - PREP_CONVERT_BLOCKS;
        const int wid = tid >> 5;
        const int lane = tid & 31;
        // Z-pack: lane L votes element e = 2L (L<16) or 2(L-16)+1 (L>=16)
        const int e = ((2 * lane) & 31) | (lane >> 4);
        #pragma unroll
        for (int j = 0; j < 8; ++j) {
            uint32_t W = (uint32_t)bb * 64 + wid * 8 + j;   // word 0..524287
            uint32_t o = W >> 7;
            uint32_t kw = W & 127;
            float v = sw[(size_t)o * IN_F + kw * 32 + e];
            uint32_t m = __ballot_sync(0xFFFFFFFFu, v < 0.0f);
            if (lane == 0) g_packT[(size_t)o * 128 + kw] = m;   // column-major kwords
        }
    } else {
        const int idx = (b - PREP_CONVERT_BLOCKS - PREP_SIGN_BLOCKS) * 256 + tid;
        const int kg = idx >> 12;
        const int o = idx & 4095;
        __half h = __float2half_rn(scales[(size_t)o * (IN_F / 128) + kg]);
        __half2 hh = __half2half2(h);
        g_ppT[(size_t)kg * OUT_F + o] = *reinterpret_cast<uint32_t*>(&hh);
    }
}

// ============================================================
// GEMM: fp16 mma.sync, CTA 128x128xBK128, 4 warps M128xN32
// Z words per column are 16B-contiguous: one LDS.128 per nj.
// B built in regs: 1 funnel-rotate + 1 LOP3 per B register.
// ============================================================
__global__ void __launch_bounds__(NTH, 2)
bitlinear_mma_kernel(float* __restrict__ out) {
    extern __shared__ char smem[];
    const uint32_t smem_base = smem_u32(smem);

    const int tid = threadIdx.x;
    const int wid = tid >> 5;            // warp -> N slice
    const int lane = tid & 31;
    const int g = lane >> 2;
    const int t = lane & 3;

    const int mt = blockIdx.x >> 5;
    const int nt = blockIdx.x & 31;
    const int m0 = mt * BM;
    const int o0 = nt * BN;

    // ---- A cp.async addressing: 2048 chunks, 16 per thread ----
    const int arow = tid >> 4;           // 0..7, covers rows arow + 8j
    const int ac = tid & 15;             // chunk 0..15
    const __half* xsrc0 = g_xh + (size_t)(m0 + arow) * IN_F + ac * 8;
    const uint32_t adst0 = (uint32_t)(arow * 256 + ((ac ^ (arow & 7)) << 4));

    float acc[8][4][4];
    #pragma unroll
    for (int mi = 0; mi < 8; ++mi)
        #pragma unroll
        for (int nj = 0; nj < 4; ++nj)
            #pragma unroll
            for (int r = 0; r < 4; ++r) acc[mi][nj][r] = 0.0f;

    // ---- ldmatrix A lane components ----
    const int a_row_l = lane & 15;       // + 16*mi, mi 0..7
    const int a_hl = lane >> 4;          // 0/1 -> chunk 2ks + hl
    const int e7 = a_row_l & 7;          // swizzle bits (mi-invariant)
    const int colb = wid * 32 + g;       // this warp's B col base
    const uint32_t off_ks0 = (uint32_t)((a_hl ^ e7) << 4);

    // rotate amounts (loop-invariant): bring Z bits (j, 16+j) to (15, 31)
    const uint32_t ra0e = (uint32_t)(t + 17);
    const uint32_t ra0o = (uint32_t)(t + 25);
    const uint32_t ra1e = (uint32_t)(t + 21);
    const uint32_t ra1o = (uint32_t)(t + 29);

    auto stage_fill = [&](int it, int s) {
        const uint32_t sb = smem_base + (uint32_t)(s * STG_STRIDE);
        const __half* src = xsrc0 + (size_t)it * BK;
        #pragma unroll
        for (int j = 0; j < 16; ++j)
            CP_ASYNC16(sb + adst0 + (uint32_t)(j * 2048),
                       (const char*)(src + (size_t)j * 8 * IN_F));
        // W: one 16B chunk (4 kwords) per column, one column per thread
        {
            const uint32_t* wsrc = g_packT + (size_t)(o0 + tid) * 128 + 4 * it;
            CP_ASYNC16(sb + STG_W + (uint32_t)(tid * 16), (const char*)wsrc);
        }
        if (tid < 32) {
            const uint32_t* ssrc = g_ppT + (size_t)it * OUT_F + o0 + tid * 4;
            CP_ASYNC16(sb + STG_S + (uint32_t)(tid * 16), (const char*)ssrc);
        }
    };

    stage_fill(0, 0);
    CP_COMMIT();

    int sa = 0;

    #pragma unroll 1
    for (int it = 0; it < KITERS; ++it) {
        if (it < KITERS - 1) {
            const int sn3 = (sa == 2) ? 0 : sa + 1;
            stage_fill(it + 1, sn3);
        }
        CP_COMMIT();
        CP_WAIT1();
        __syncthreads();

        const uint32_t abase = smem_base + (uint32_t)(sa * STG_STRIDE)
                             + (uint32_t)(a_row_l * 256);

        // ---- issue first A fragment batch IMMEDIATELY post-barrier ----
        uint32_t af[2][8][4];
        #pragma unroll
        for (int mi = 0; mi < 8; ++mi)
            ldsm_x4(af[0][mi], abase + (uint32_t)(mi * 4096) + off_ks0);

        // ---- Z words (one LDS.128 per nj) + scale word, this lane's 4 cols ----
        uint32_t w[4][4], pp[4];
        {
            const char* st = smem + sa * STG_STRIDE;
            const uint32_t* Sp = reinterpret_cast<const uint32_t*>(st + STG_S);
            #pragma unroll
            for (int nj = 0; nj < 4; ++nj) {
                const int c = colb + nj * 8;
                uint4 z4 = *reinterpret_cast<const uint4*>(st + STG_W + c * 16);
                w[0][nj] = z4.x;
                w[1][nj] = z4.y;
                w[2][nj] = z4.z;
                w[3][nj] = z4.w;
                pp[nj] = Sp[c];
            }
        }

        #pragma unroll
        for (int ks = 0; ks < 8; ++ks) {
            const int cur = ks & 1;
            if (ks < 7) {
                const uint32_t offn = (uint32_t)(((2 * (ks + 1) + a_hl) ^ e7) << 4);
                #pragma unroll
                for (int mi = 0; mi < 8; ++mi)
                    ldsm_x4(af[cur ^ 1][mi], abase + (uint32_t)(mi * 4096) + offn);
            }
            const int kw = ks >> 1;
            const uint32_t aE = (ks & 1) ? ra0o : ra0e;
            const uint32_t aO = (ks & 1) ? ra1o : ra1e;

            #pragma unroll
            for (int nj = 0; nj < 4; ++nj) {
                const uint32_t z = w[kw][nj];
                const uint32_t r0 = __funnelshift_r(z, z, aE);
                const uint32_t r1 = __funnelshift_r(z, z, aO);
                const uint32_t b0 = (r0 & 0x80008000u) ^ pp[nj];
                const uint32_t b1 = (r1 & 0x80008000u) ^ pp[nj];
                #pragma unroll
                for (int mi = 0; mi < 8; ++mi)
                    mma_fp16(acc[mi][nj], af[cur][mi], b0, b1);
            }
        }

        sa = (sa == 2) ? 0 : sa + 1;
    }

    // ---- epilogue: direct STG.64 ----
    #pragma unroll
    for (int mi = 0; mi < 8; ++mi) {
        const int row = m0 + mi * 16 + g;
        #pragma unroll
        for (int nj = 0; nj < 4; ++nj) {
            const int col = o0 + wid * 32 + nj * 8 + 2 * t;
            float2 v0 = make_float2(acc[mi][nj][0], acc[mi][nj][1]);
            float2 v1 = make_float2(acc[mi][nj][2], acc[mi][nj][3]);
            *reinterpret_cast<float2*>(out + (size_t)row * OUT_F + col) = v0;
            *reinterpret_cast<float2*>(out + (size_t)(row + 8) * OUT_F + col) = v1;
        }
    }
}

// ============================================================
// launch
// ============================================================
extern "C" void kernel_launch(void* const* d_in, const int* in_sizes, int n_in,
                              void* d_out, int out_size) {
    const float* x      = (const float*)d_in[0];
    const float* sw     = (const float*)d_in[1];
    const float* scales = (const float*)d_in[2];
    float* out = (float*)d_out;

    cudaFuncSetAttribute(bitlinear_mma_kernel,
                         cudaFuncAttributeMaxDynamicSharedMemorySize, SM_TOTAL);

    prep_kernel<<<PREP_GRID, 256>>>((const float4*)x, sw, scales);

    // 64 M-tiles x 32 N-tiles
    bitlinear_mma_kernel<<<(M_TOT / BM) * (OUT_F / BN), NTH, SM_TOTAL>>>(out);
}

// round 17
// speedup vs baseline: 1.0360x; 1.0360x over previous
#include <cuda_runtime.h>
#include <cuda_fp16.h>
#include <cstdint>

// ---------------- problem constants ----------------
#define IN_F   4096
#define OUT_F  4096
#define M_TOT  8192
#define BK     128          // k per iteration (= one scale group, 256B rows)
#define KITERS (IN_F / BK)  // 32
#define BM     128
#define BN     128
#define NTH    128          // 4 warps, each M128 x N32

// ---------------- static device scratch ----------------
// Z-packed inverted sign words, transposed: g_packT[kw*4096 + o]
//   bit j    (j<16) = 1 iff weight(o, 32kw + 2j)   < 0
//   bit 16+j (j<16) = 1 iff weight(o, 32kw + 2j+1) < 0
__device__ uint32_t g_packT[(size_t)(IN_F / 32) * OUT_F];   // 2 MB
__device__ __half   g_xh[(size_t)M_TOT * IN_F];             // 64 MB
// per (kgroup, o): half2(s, s) as uint32, transposed [kg][o]
__device__ uint32_t g_ppT[(size_t)(IN_F / 128) * OUT_F];    // 512 KB

// ---------------- SMEM stage layout (bytes) ----------------
// A: 32768 (128 rows x 256B, 16 chunks, xor-8 swizzle)
// W: 2048  (4 kwords x 128 cols x 4B)
// S: 512   (128 cols x 4B half2 scale)
#define STG_A      0
#define STG_W      32768
#define STG_S      34816
#define STG_STRIDE 35328
#define STAGES     3
#define SM_TOTAL   (STAGES * STG_STRIDE)   // 105984

// ---------------- helpers ----------------
static __device__ __forceinline__ uint32_t smem_u32(const void* p) {
    uint32_t a;
    asm("{ .reg .u64 t; cvta.to.shared.u64 t, %1; cvt.u32.u64 %0, t; }"
        : "=r"(a) : "l"(p));
    return a;
}

#define CP_ASYNC16(dst, src) \
    asm volatile("cp.async.cg.shared.global [%0], [%1], 16;" :: "r"(dst), "l"(src))
#define CP_COMMIT()  asm volatile("cp.async.commit_group;" ::: "memory")
#define CP_WAIT1()   asm volatile("cp.async.wait_group 1;" ::: "memory")

static __device__ __forceinline__ void ldsm_x4(uint32_t* r, uint32_t addr) {
    asm volatile("ldmatrix.sync.aligned.m8n8.x4.shared.b16 {%0,%1,%2,%3}, [%4];"
                 : "=r"(r[0]), "=r"(r[1]), "=r"(r[2]), "=r"(r[3]) : "r"(addr));
}

static __device__ __forceinline__ void mma_fp16(float* d, const uint32_t* a,
                                                uint32_t b0, uint32_t b1) {
    asm("mma.sync.aligned.m16n8k16.row.col.f32.f16.f16.f32 "
        "{%0,%1,%2,%3}, {%4,%5,%6,%7}, {%8,%9}, {%0,%1,%2,%3};"
        : "+f"(d[0]), "+f"(d[1]), "+f"(d[2]), "+f"(d[3])
        : "r"(a[0]), "r"(a[1]), "r"(a[2]), "r"(a[3]), "r"(b0), "r"(b1));
}

// ============================================================
// Fused prep kernel, grid-sectioned (scale pack folded into sign blocks)
// ============================================================
#define PREP_CONVERT_BLOCKS 16384
#define PREP_SIGN_BLOCKS    8192
#define PREP_GRID (PREP_CONVERT_BLOCKS + PREP_SIGN_BLOCKS)

__global__ void __launch_bounds__(256)
prep_kernel(const float4* __restrict__ x4,
            const float* __restrict__ sw,
            const float* __restrict__ scales) {
    const int b = blockIdx.x;
    const int tid = threadIdx.x;

    if (b < PREP_CONVERT_BLOCKS) {
        size_t i = (size_t)b * 256 + tid;        // 8 floats each
        float4 a = x4[2 * i];
        float4 c = x4[2 * i + 1];
        __half2 h0 = __floats2half2_rn(a.x, a.y);
        __half2 h1 = __floats2half2_rn(a.z, a.w);
        __half2 h2 = __floats2half2_rn(c.x, c.y);
        __half2 h3 = __floats2half2_rn(c.z, c.w);
        uint4 q;
        q.x = *reinterpret_cast<uint32_t*>(&h0);
        q.y = *reinterpret_cast<uint32_t*>(&h1);
        q.z = *reinterpret_cast<uint32_t*>(&h2);
        q.w = *reinterpret_cast<uint32_t*>(&h3);
        *reinterpret_cast<uint4*>(&g_xh[i * 8]) = q;
    } else {
        const int bb = b - PREP_CONVERT_BLOCKS;
        const int wid = tid >> 5;
        const int lane = tid & 31;
        // Z-pack: lane L votes element e = 2L (L<16) or 2(L-16)+1 (L>=16)
        const int e = ((2 * lane) & 31) | (lane >> 4);
        #pragma unroll
        for (int j = 0; j < 8; ++j) {
            uint32_t W = (uint32_t)bb * 64 + wid * 8 + j;   // word 0..524287
            uint32_t o = W >> 7;
            uint32_t kw = W & 127;
            float v = sw[(size_t)o * IN_F + kw * 32 + e];
            uint32_t m = __ballot_sync(0xFFFFFFFFu, v < 0.0f);
            if (lane == 0) g_packT[(size_t)kw * OUT_F + o] = m;
        }
        // scale pack folded in: first 512 sign blocks each handle 256 entries
        if (bb < 512) {
            const int idx = bb * 256 + tid;      // 0..131071
            const int kg = idx >> 12;
            const int o = idx & 4095;
            __half h = __float2half_rn(scales[(size_t)o * (IN_F / 128) + kg]);
            __half2 hh = __half2half2(h);
            g_ppT[(size_t)kg * OUT_F + o] = *reinterpret_cast<uint32_t*>(&hh);
        }
    }
}

// ============================================================
// GEMM: fp16 mma.sync, CTA 128x128xBK128, 4 warps M128xN32
// (R13 configuration — measured optimum: 559us, 80.9% tensor)
// ============================================================
__global__ void __launch_bounds__(NTH, 2)
bitlinear_mma_kernel(float* __restrict__ out) {
    extern __shared__ char smem[];
    const uint32_t smem_base = smem_u32(smem);

    const int tid = threadIdx.x;
    const int wid = tid >> 5;            // warp -> N slice
    const int lane = tid & 31;
    const int g = lane >> 2;
    const int t = lane & 3;

    const int mt = blockIdx.x >> 5;
    const int nt = blockIdx.x & 31;
    const int m0 = mt * BM;
    const int o0 = nt * BN;

    // ---- A cp.async addressing: 2048 chunks, 16 per thread ----
    const int arow = tid >> 4;           // 0..7, covers rows arow + 8j
    const int ac = tid & 15;             // chunk 0..15
    const __half* xsrc0 = g_xh + (size_t)(m0 + arow) * IN_F + ac * 8;
    const uint32_t adst0 = (uint32_t)(arow * 256 + ((ac ^ (arow & 7)) << 4));

    // ---- W/S cp.async addressing ----
    const int wkw = tid >> 5;            // kword 0..3
    const int wcg = tid & 31;            // col group

    float acc[8][4][4];
    #pragma unroll
    for (int mi = 0; mi < 8; ++mi)
        #pragma unroll
        for (int nj = 0; nj < 4; ++nj)
            #pragma unroll
            for (int r = 0; r < 4; ++r) acc[mi][nj][r] = 0.0f;

    // ---- ldmatrix A lane components ----
    const int a_row_l = lane & 15;       // + 16*mi, mi 0..7
    const int a_hl = lane >> 4;          // 0/1 -> chunk 2ks + hl
    const int e7 = a_row_l & 7;          // swizzle bits (mi-invariant)
    const int colb = wid * 32 + g;       // this warp's B col base

    // rotate amounts (loop-invariant): bring Z bits (j, 16+j) to (15, 31)
    const uint32_t ra0e = (uint32_t)(t + 17);
    const uint32_t ra0o = (uint32_t)(t + 25);
    const uint32_t ra1e = (uint32_t)(t + 21);
    const uint32_t ra1o = (uint32_t)(t + 29);

    auto stage_fill = [&](int it, int s) {
        const uint32_t sb = smem_base + (uint32_t)(s * STG_STRIDE);
        const __half* src = xsrc0 + (size_t)it * BK;
        #pragma unroll
        for (int j = 0; j < 16; ++j)
            CP_ASYNC16(sb + adst0 + (uint32_t)(j * 2048),
                       (const char*)(src + (size_t)j * 8 * IN_F));
        {
            const uint32_t* wsrc = g_packT + (size_t)(4 * it + wkw) * OUT_F + o0 + wcg * 4;
            CP_ASYNC16(sb + STG_W + (uint32_t)(tid * 16), (const char*)wsrc);
        }
        if (tid < 32) {
            const uint32_t* ssrc = g_ppT + (size_t)it * OUT_F + o0 + tid * 4;
            CP_ASYNC16(sb + STG_S + (uint32_t)(tid * 16), (const char*)ssrc);
        }
    };

    stage_fill(0, 0);
    CP_COMMIT();

    int sa = 0;

    #pragma unroll 1
    for (int it = 0; it < KITERS; ++it) {
        if (it < KITERS - 1) {
            const int sn3 = (sa == 2) ? 0 : sa + 1;
            stage_fill(it + 1, sn3);
        }
        CP_COMMIT();
        CP_WAIT1();
        __syncthreads();

        const char* st = smem + sa * STG_STRIDE;
        const uint32_t abase = smem_base + (uint32_t)(sa * STG_STRIDE)
                             + (uint32_t)(a_row_l * 256);

        // ---- Z words (4 kwords) + scale word for this lane's 4 cols ----
        uint32_t w[4][4], pp[4];
        {
            const uint32_t* Wp = reinterpret_cast<const uint32_t*>(st + STG_W);
            const uint32_t* Sp = reinterpret_cast<const uint32_t*>(st + STG_S);
            #pragma unroll
            for (int nj = 0; nj < 4; ++nj) {
                const int c = colb + nj * 8;
                w[0][nj] = Wp[c];
                w[1][nj] = Wp[128 + c];
                w[2][nj] = Wp[256 + c];
                w[3][nj] = Wp[384 + c];
                pp[nj] = Sp[c];
            }
        }

        // ---- software-pipelined A fragments across 8 ksteps ----
        uint32_t af[2][8][4];
        {
            const uint32_t off0 = (uint32_t)((a_hl ^ e7) << 4);
            #pragma unroll
            for (int mi = 0; mi < 8; ++mi)
                ldsm_x4(af[0][mi], abase + (uint32_t)(mi * 4096) + off0);
        }

        #pragma unroll
        for (int ks = 0; ks < 8; ++ks) {
            const int cur = ks & 1;
            if (ks < 7) {
                const uint32_t offn = (uint32_t)(((2 * (ks + 1) + a_hl) ^ e7) << 4);
                #pragma unroll
                for (int mi = 0; mi < 8; ++mi)
                    ldsm_x4(af[cur ^ 1][mi], abase + (uint32_t)(mi * 4096) + offn);
            }
            const int kw = ks >> 1;
            const uint32_t aE = (ks & 1) ? ra0o : ra0e;
            const uint32_t aO = (ks & 1) ? ra1o : ra1e;

            #pragma unroll
            for (int nj = 0; nj < 4; ++nj) {
                const uint32_t z = w[kw][nj];
                const uint32_t r0 = __funnelshift_r(z, z, aE);
                const uint32_t r1 = __funnelshift_r(z, z, aO);
                const uint32_t b0 = (r0 & 0x80008000u) ^ pp[nj];
                const uint32_t b1 = (r1 & 0x80008000u) ^ pp[nj];
                #pragma unroll
                for (int mi = 0; mi < 8; ++mi)
                    mma_fp16(acc[mi][nj], af[cur][mi], b0, b1);
            }
        }

        sa = (sa == 2) ? 0 : sa + 1;
    }

    // ---- epilogue: direct STG.64 ----
    #pragma unroll
    for (int mi = 0; mi < 8; ++mi) {
        const int row = m0 + mi * 16 + g;
        #pragma unroll
        for (int nj = 0; nj < 4; ++nj) {
            const int col = o0 + wid * 32 + nj * 8 + 2 * t;
            float2 v0 = make_float2(acc[mi][nj][0], acc[mi][nj][1]);
            float2 v1 = make_float2(acc[mi][nj][2], acc[mi][nj][3]);
            *reinterpret_cast<float2*>(out + (size_t)row * OUT_F + col) = v0;
            *reinterpret_cast<float2*>(out + (size_t)(row + 8) * OUT_F + col) = v1;
        }
    }
}

// ============================================================
// launch
// ============================================================
extern "C" void kernel_launch(void* const* d_in, const int* in_sizes, int n_in,
                              void* d_out, int out_size) {
    const float* x      = (const float*)d_in[0];
    const float* sw     = (const float*)d_in[1];
    const float* scales = (const float*)d_in[2];
    float* out = (float*)d_out;

    cudaFuncSetAttribute(bitlinear_mma_kernel,
                         cudaFuncAttributeMaxDynamicSharedMemorySize, SM_TOTAL);

    prep_kernel<<<PREP_GRID, 256>>>((const float4*)x, sw, scales);

    // 64 M-tiles x 32 N-tiles
    bitlinear_mma_kernel<<<(M_TOT / BM) * (OUT_F / BN), NTH, SM_TOTAL>>>(out);
}